// round 4
// baseline (speedup 1.0000x reference)
#include <cuda_runtime.h>
#include <cuda_bf16.h>
#include <cstdint>
#include <cstddef>

// ---------------------------------------------------------------------------
// Problem constants
// ---------------------------------------------------------------------------
#define HN   1024
#define SN   8192
#define TN   48
#define START_TAG 46
#define END_TAG   47
#define NEGV (-10000.0f)

// ---------------------------------------------------------------------------
// Scratch (device globals; no runtime allocation allowed)
// ---------------------------------------------------------------------------
__device__ float g_XI[2][SN][4 * HN];     // precomputed x@W_ih^T + biases (dir b stored in step order)
__device__ float g_Hseq[2][SN][HN];       // h sequences, dir 1 already reversed to sentence order
__device__ float g_Hbuf[2][2][HN];        // [dir][parity][j] recurrent h exchange
__device__ float g_feats[SN * TN];
__device__ unsigned char g_bp[SN * TN];
__device__ unsigned int g_bar_cnt;
__device__ volatile unsigned int g_bar_gen;

// ---------------------------------------------------------------------------
// Init: zero recurrent state + reset grid barrier (must run each launch)
// ---------------------------------------------------------------------------
__global__ void init_kernel() {
    int tid = threadIdx.x;
    float* hb = &g_Hbuf[0][0][0];
    for (int i = tid; i < 2 * 2 * HN; i += blockDim.x) hb[i] = 0.0f;
    if (tid == 0) { g_bar_cnt = 0; g_bar_gen = 0; }
}

// ---------------------------------------------------------------------------
// Kernel A: XI = x @ W_ih^T + (b_ih + b_hh)  for both directions.
// z=0: forward, rows in order. z=1: backward, output row = SN-1-m (so XI[1][t]
// corresponds to x[SN-1-t], i.e. the reversed input the backward LSTM sees).
// Tiled SGEMM: BM=BN=128, BK=16, 256 threads, 8x8 microtile.
// ---------------------------------------------------------------------------
#define BM 128
#define BN 128
#define BK 16

__global__ void __launch_bounds__(256) xi_gemm_kernel(
    const float* __restrict__ x,
    const float* __restrict__ Wf, const float* __restrict__ Wb,
    const float* __restrict__ bihf, const float* __restrict__ bhhf,
    const float* __restrict__ bihb, const float* __restrict__ bhhb)
{
    __shared__ float As[BK][BM + 4];
    __shared__ float Bs[BK][BN + 4];

    const int z  = blockIdx.z;
    const float* W  = z ? Wb   : Wf;
    const float* b1 = z ? bihb : bihf;
    const float* b2 = z ? bhhb : bhhf;

    const int m0 = blockIdx.y * BM;
    const int n0 = blockIdx.x * BN;
    const int tid = threadIdx.x;

    const int lr = tid >> 2;          // 0..63
    const int lc = (tid & 3) << 2;    // 0,4,8,12
    const int ty = tid >> 4;          // 0..15
    const int tx = tid & 15;          // 0..15

    float acc[8][8];
#pragma unroll
    for (int i = 0; i < 8; i++)
#pragma unroll
        for (int j = 0; j < 8; j++) acc[i][j] = 0.0f;

    for (int k0 = 0; k0 < HN; k0 += BK) {
        // load A tile (x) and B tile (W), both K-major [row, k]
        float4 va0 = *(const float4*)&x[(size_t)(m0 + lr)       * HN + k0 + lc];
        float4 va1 = *(const float4*)&x[(size_t)(m0 + lr + 64)  * HN + k0 + lc];
        float4 vb0 = *(const float4*)&W[(size_t)(n0 + lr)       * HN + k0 + lc];
        float4 vb1 = *(const float4*)&W[(size_t)(n0 + lr + 64)  * HN + k0 + lc];

        As[lc + 0][lr] = va0.x; As[lc + 1][lr] = va0.y; As[lc + 2][lr] = va0.z; As[lc + 3][lr] = va0.w;
        As[lc + 0][lr + 64] = va1.x; As[lc + 1][lr + 64] = va1.y; As[lc + 2][lr + 64] = va1.z; As[lc + 3][lr + 64] = va1.w;
        Bs[lc + 0][lr] = vb0.x; Bs[lc + 1][lr] = vb0.y; Bs[lc + 2][lr] = vb0.z; Bs[lc + 3][lr] = vb0.w;
        Bs[lc + 0][lr + 64] = vb1.x; Bs[lc + 1][lr + 64] = vb1.y; Bs[lc + 2][lr + 64] = vb1.z; Bs[lc + 3][lr + 64] = vb1.w;
        __syncthreads();

#pragma unroll
        for (int kk = 0; kk < BK; kk++) {
            float a[8], b[8];
            *(float4*)&a[0] = *(const float4*)&As[kk][ty * 8];
            *(float4*)&a[4] = *(const float4*)&As[kk][ty * 8 + 4];
            *(float4*)&b[0] = *(const float4*)&Bs[kk][tx * 8];
            *(float4*)&b[4] = *(const float4*)&Bs[kk][tx * 8 + 4];
#pragma unroll
            for (int i = 0; i < 8; i++)
#pragma unroll
                for (int j = 0; j < 8; j++) acc[i][j] += a[i] * b[j];
        }
        __syncthreads();
    }

    // epilogue: add bias, reverse row for backward direction
    float bias[8];
#pragma unroll
    for (int j = 0; j < 8; j++) {
        int n = n0 + tx * 8 + j;
        bias[j] = b1[n] + b2[n];
    }
#pragma unroll
    for (int i = 0; i < 8; i++) {
        int m = m0 + ty * 8 + i;
        int row = z ? (SN - 1 - m) : m;
        float* outr = &g_XI[z][row][0];
#pragma unroll
        for (int j = 0; j < 8; j++) {
            int n = n0 + tx * 8 + j;
            outr[n] = acc[i][j] + bias[j];
        }
    }
}

// ---------------------------------------------------------------------------
// Kernel B: persistent BiLSTM recurrence.
// 128 blocks x 256 threads. Block b: dir = b>>6, h-outputs [jbase, jbase+16).
// 64 gate rows/block; warp w owns rows [8w, 8w+8): 4 rows register-resident,
// 4 rows SMEM-resident. Lane l owns K-chunks k = 4l + 128m (+c), m=0..7.
// Grid barrier per step via single-address atomic + volatile generation flag.
// ---------------------------------------------------------------------------
#define NBLK 128
#define OPB  16
#define LSTM_SMEM ((32 * 1024 + 1024 + 64) * 4)

__device__ __forceinline__ float sigf(float x) { return 1.0f / (1.0f + __expf(-x)); }

__global__ void __launch_bounds__(256, 1) lstm_kernel(
    const float* __restrict__ Whh_f, const float* __restrict__ Whh_b)
{
    extern __shared__ float sm[];
    float* wsh  = sm;                    // 32*1024 floats (smem-resident rows)
    float* hs   = sm + 32 * 1024;        // 1024 floats (h_prev)
    float* gsum = hs + 1024;             // 64 row sums

    const int tid  = threadIdx.x;
    const int w    = tid >> 5;
    const int lane = tid & 31;
    const int b    = blockIdx.x;
    const int dir  = b >> 6;
    const int jbase = (b & 63) * OPB;
    const float* Whh = dir ? Whh_b : Whh_f;

    // -------- load weights: rows 8w..8w+3 -> regs, 8w+4..8w+7 -> smem -------
    float4 wr[4][8];
#pragma unroll
    for (int q = 0; q < 4; q++) {
        int rr = 8 * w + q;
        int grow = (rr >> 4) * HN + jbase + (rr & 15);
        const float4* src = (const float4*)(Whh + (size_t)grow * HN);
#pragma unroll
        for (int m = 0; m < 8; m++) wr[q][m] = src[lane + 32 * m];
    }
#pragma unroll
    for (int q = 0; q < 4; q++) {
        int rr = 8 * w + 4 + q;
        int grow = (rr >> 4) * HN + jbase + (rr & 15);
        const float4* src = (const float4*)(Whh + (size_t)grow * HN);
        float4* dst = (float4*)(wsh + (size_t)(w * 4 + q) * HN);
#pragma unroll
        for (int m = 0; m < 8; m++) dst[lane + 32 * m] = src[lane + 32 * m];
    }

    float c_state = 0.0f;

    for (int t = 0; t < SN; t++) {
        // prefetch xi for this step's gate assembly (threads 0..15)
        float xi0 = 0.f, xi1 = 0.f, xi2 = 0.f, xi3 = 0.f;
        if (tid < OPB) {
            const float* xr = &g_XI[dir][t][0];
            xi0 = __ldg(xr + 0 * HN + jbase + tid);
            xi1 = __ldg(xr + 1 * HN + jbase + tid);
            xi2 = __ldg(xr + 2 * HN + jbase + tid);
            xi3 = __ldg(xr + 3 * HN + jbase + tid);
        }

        // load h_prev (bypass L1: another SM wrote it last step)
        {
            const float4* hb4 = (const float4*)&g_Hbuf[dir][t & 1][0];
            float4 v = __ldcg(hb4 + tid);
            ((float4*)hs)[tid] = v;
        }
        __syncthreads();

        // h chunk into registers
        float4 hv[8];
#pragma unroll
        for (int m = 0; m < 8; m++) hv[m] = ((const float4*)hs)[lane + 32 * m];

        float acc[8];
#pragma unroll
        for (int r = 0; r < 8; r++) acc[r] = 0.0f;

        // register-resident rows
#pragma unroll
        for (int q = 0; q < 4; q++) {
#pragma unroll
            for (int m = 0; m < 8; m++) {
                float4 ww = wr[q][m];
                acc[q] += ww.x * hv[m].x + ww.y * hv[m].y + ww.z * hv[m].z + ww.w * hv[m].w;
            }
        }
        // smem-resident rows
#pragma unroll
        for (int q = 0; q < 4; q++) {
            const float4* wp = (const float4*)(wsh + (size_t)(w * 4 + q) * HN);
            float a = 0.0f;
#pragma unroll
            for (int m = 0; m < 8; m++) {
                float4 ww = wp[lane + 32 * m];
                a += ww.x * hv[m].x + ww.y * hv[m].y + ww.z * hv[m].z + ww.w * hv[m].w;
            }
            acc[4 + q] = a;
        }

        // warp reduction over K
#pragma unroll
        for (int r = 0; r < 8; r++) {
#pragma unroll
            for (int o = 16; o > 0; o >>= 1)
                acc[r] += __shfl_xor_sync(0xffffffffu, acc[r], o);
        }
        if (lane == 0) {
#pragma unroll
            for (int r = 0; r < 8; r++) gsum[8 * w + r] = acc[r];
        }
        __syncthreads();

        // gate assembly + cell update (threads 0..15)
        if (tid < OPB) {
            float gi = gsum[tid]          + xi0;
            float gf = gsum[16 + tid]     + xi1;
            float gg = gsum[32 + tid]     + xi2;
            float go = gsum[48 + tid]     + xi3;
            float si = sigf(gi);
            float sf = sigf(gf);
            float tg = tanhf(gg);
            float so = sigf(go);
            c_state = sf * c_state + si * tg;
            float hout = so * tanhf(c_state);
            int j = jbase + tid;
            g_Hbuf[dir][(t + 1) & 1][j] = hout;
            int srow = dir ? (SN - 1 - t) : t;
            g_Hseq[dir][srow][j] = hout;
        }

        // ---------------- grid barrier ----------------
        __syncthreads();
        if (tid == 0) {
            __threadfence();
            unsigned prev = atomicAdd(&g_bar_cnt, 1u);
            if (prev == NBLK - 1) {
                g_bar_cnt = 0;
                __threadfence();
                g_bar_gen = (unsigned)(t + 1);
            } else {
                while (g_bar_gen <= (unsigned)t) { }
            }
        }
        __syncthreads();
    }
}

// ---------------------------------------------------------------------------
// Kernel C: feats = concat(hf, hb) @ W_dense^T + b_dense.  4 rows per block.
// ---------------------------------------------------------------------------
__global__ void __launch_bounds__(256) dense_kernel(
    const float* __restrict__ Wd, const float* __restrict__ bd)
{
    __shared__ float hsm[4][2 * HN];
    const int tid  = threadIdx.x;
    const int w    = tid >> 5;
    const int lane = tid & 31;
    const int s0   = blockIdx.x * 4;

    for (int i = tid; i < 4 * 512; i += 256) {
        int r = i >> 9, f4 = i & 511;
        float4 v;
        if (f4 < 256) v = *(const float4*)&g_Hseq[0][s0 + r][f4 * 4];
        else          v = *(const float4*)&g_Hseq[1][s0 + r][(f4 - 256) * 4];
        *(float4*)&hsm[r][f4 * 4] = v;
    }
    __syncthreads();

    for (int idx = w; idx < 4 * TN; idx += 8) {
        int r = idx / TN, tag = idx - r * TN;
        const float4* wrow = (const float4*)(Wd + (size_t)tag * 2 * HN);
        const float4* hrow = (const float4*)&hsm[r][0];
        float acc = 0.0f;
#pragma unroll
        for (int m = 0; m < 16; m++) {
            float4 a  = wrow[lane + 32 * m];
            float4 h4 = hrow[lane + 32 * m];
            acc += a.x * h4.x + a.y * h4.y + a.z * h4.z + a.w * h4.w;
        }
#pragma unroll
        for (int o = 16; o > 0; o >>= 1) acc += __shfl_xor_sync(0xffffffffu, acc, o);
        if (lane == 0) g_feats[(s0 + r) * TN + tag] = acc + __ldg(&bd[tag]);
    }
}

// ---------------------------------------------------------------------------
// Kernel D: Viterbi forward + backtrack. Single block.
// Replicates jnp.argmax first-max tie-breaking (strict >, ascending j).
// Output: out[0] = path_score, out[1+s] = (float)best_path[s].
// ---------------------------------------------------------------------------
__global__ void __launch_bounds__(64) viterbi_kernel(
    const float* __restrict__ trans, float* __restrict__ out, int out_size)
{
    __shared__ float ts[TN * TN];
    __shared__ float fv[TN];
    __shared__ float fvn[TN];
    const int tid = threadIdx.x;

    for (int i = tid; i < TN * TN; i += 64) ts[i] = trans[i];
    if (tid < TN) fv[tid] = (tid == START_TAG) ? 0.0f : NEGV;
    __syncthreads();

    for (int s = 0; s < SN; s++) {
        float feat = 0.0f;
        if (tid < TN) feat = __ldg(&g_feats[s * TN + tid]);  // issued early; used after max loop
        if (tid < TN) {
            const float* tr = &ts[tid * TN];
            float best = -__int_as_float(0x7f800000);  // -inf
            int arg = 0;
#pragma unroll 8
            for (int j = 0; j < TN; j++) {
                float v = fv[j] + tr[j];
                if (v > best) { best = v; arg = j; }
            }
            fvn[tid] = best + feat;
            g_bp[s * TN + tid] = (unsigned char)arg;
        }
        __syncthreads();
        if (tid < TN) fv[tid] = fvn[tid];
        __syncthreads();
    }

    if (tid == 0) {
        float best = -__int_as_float(0x7f800000);
        int arg = 0;
        for (int i = 0; i < TN; i++) {
            float v = fv[i] + ts[END_TAG * TN + i];
            if (v > best) { best = v; arg = i; }
        }
        if (out_size > 0) out[0] = best;
        int cur = arg;
        if (SN < out_size) out[SN] = (float)cur;   // out[1 + (SN-1)]
        for (int s = SN - 1; s >= 1; s--) {
            cur = (int)g_bp[s * TN + cur];
            if (s < out_size) out[s] = (float)cur; // out[1 + (s-1)]
        }
    }
}

// ---------------------------------------------------------------------------
// Launch
// ---------------------------------------------------------------------------
extern "C" void kernel_launch(void* const* d_in, const int* in_sizes, int n_in,
                              void* d_out, int out_size)
{
    const float* sentence    = (const float*)d_in[0];
    const float* W_ih_f      = (const float*)d_in[1];
    const float* W_hh_f      = (const float*)d_in[2];
    const float* b_ih_f      = (const float*)d_in[3];
    const float* b_hh_f      = (const float*)d_in[4];
    const float* W_ih_b      = (const float*)d_in[5];
    const float* W_hh_b      = (const float*)d_in[6];
    const float* b_ih_b      = (const float*)d_in[7];
    const float* b_hh_b      = (const float*)d_in[8];
    const float* W_dense     = (const float*)d_in[9];
    const float* b_dense     = (const float*)d_in[10];
    const float* transitions = (const float*)d_in[11];
    float* out = (float*)d_out;

    (void)in_sizes; (void)n_in;

    // idempotent, host-side, capture-safe
    cudaFuncSetAttribute(lstm_kernel, cudaFuncAttributeMaxDynamicSharedMemorySize, LSTM_SMEM);

    init_kernel<<<1, 256>>>();

    dim3 ggemm(4 * HN / BN, SN / BM, 2);
    xi_gemm_kernel<<<ggemm, 256>>>(sentence, W_hh_f == nullptr ? nullptr : W_ih_f, W_ih_b,
                                   b_ih_f, b_hh_f, b_ih_b, b_hh_b);

    lstm_kernel<<<NBLK, 256, LSTM_SMEM>>>(W_hh_f, W_hh_b);

    dense_kernel<<<SN / 4, 256>>>(W_dense, b_dense);

    viterbi_kernel<<<1, 64>>>(transitions, out, out_size);
}